// round 2
// baseline (speedup 1.0000x reference)
#include <cuda_runtime.h>
#include <math.h>

// Problem constants
#define NN   512
#define HID  1024
#define OUTD 131328          // N + N*(N-1)/2
#define OUT4 (OUTD / 4)      // 32832 float4 columns

// Device scratch (no allocation allowed). Referenced ONLY in device code.
__device__ float g_h[3][HID];     // h0, h1, h2
__device__ float g_o[OUTD];
__device__ float g_L[NN * NN];

// ---------------------------------------------------------------------------
// MLP layer: out[j] = tanh(b[j] + sum_i x[i] * W[i][j]),  W row-major [IN,1024]
// Block = 256 threads (8 warps). Warp w covers i in [w*IN/8, (w+1)*IN/8).
// Each lane owns output column j = blockIdx.x*32 + lane (coalesced W reads).
// SRC: -1 = external x pointer, else g_h[SRC]. DST: index into g_h.
// ---------------------------------------------------------------------------
template <int IN, int SRC, int DST>
__global__ void mlp_layer(const float* __restrict__ x_ext,
                          const float* __restrict__ W,
                          const float* __restrict__ b) {
    const float* x = (SRC < 0) ? x_ext : g_h[SRC];
    const int lane = threadIdx.x & 31;
    const int w    = threadIdx.x >> 5;
    const int j    = blockIdx.x * 32 + lane;
    const int CH   = IN / 8;
    const int i0   = w * CH;

    float acc = 0.f;
#pragma unroll 8
    for (int i = 0; i < CH; ++i) {
        acc += x[i0 + i] * __ldg(&W[(size_t)(i0 + i) * 1024 + j]);
    }

    __shared__ float sh[8][32];
    sh[w][lane] = acc;
    __syncthreads();
    if (w == 0) {
        float s = 0.f;
#pragma unroll
        for (int q = 0; q < 8; ++q) s += sh[q][lane];
        g_h[DST][j] = tanhf(s + __ldg(&b[j]));
    }
}

// ---------------------------------------------------------------------------
// Big GEMV: o[k] = bo[k] + sum_j h2[j] * Wo[j][k],  Wo row-major [1024, OUTD]
// One float4 column per thread; h2 staged in shared; unrolled j loop for MLP.
// ---------------------------------------------------------------------------
__global__ void gemv_out(const float* __restrict__ Wo,
                         const float* __restrict__ bo) {
    __shared__ float hs[HID];
    for (int t = threadIdx.x; t < HID; t += blockDim.x) hs[t] = g_h[2][t];
    __syncthreads();

    const int k4 = blockIdx.x * blockDim.x + threadIdx.x;
    if (k4 >= OUT4) return;

    const float4* W4 = (const float4*)Wo;
    float ax = 0.f, ay = 0.f, az = 0.f, aw = 0.f;

#pragma unroll 8
    for (int j = 0; j < HID; ++j) {
        float4 wv = __ldg(&W4[(size_t)j * OUT4 + k4]);
        float  hj = hs[j];
        ax += hj * wv.x;
        ay += hj * wv.y;
        az += hj * wv.z;
        aw += hj * wv.w;
    }

    float4 bv = __ldg(&((const float4*)bo)[k4]);
    float4 r;
    r.x = ax + bv.x; r.y = ay + bv.y; r.z = az + bv.z; r.w = aw + bv.w;
    ((float4*)g_o)[k4] = r;
}

// ---------------------------------------------------------------------------
// Assemble L: diag = exp(o[:N]); strict lower from o[N:] in tril-index order.
// ---------------------------------------------------------------------------
__global__ void build_L() {
    const int idx = blockIdx.x * 256 + threadIdx.x;   // < 512*512
    const int r = idx >> 9;
    const int c = idx & 511;
    float v;
    if (c < r)       v = g_o[NN + (r * (r - 1)) / 2 + c];
    else if (c == r) v = expf(g_o[r]);
    else             v = 0.f;
    g_L[idx] = v;
}

// ---------------------------------------------------------------------------
// D = L * L^T (symmetric). 32x32 output tiles; grid 16x16 but upper-triangle
// blocks exit immediately; lower/diag blocks computed, off-diag mirrored on
// store. Each thread computes a 2x2 microtile.
// ---------------------------------------------------------------------------
__global__ void gemm_llt(float* __restrict__ D) {
    const int bi = blockIdx.y;   // row tile
    const int bj = blockIdx.x;   // col tile
    if (bj > bi) return;

    __shared__ float As[32][33];
    __shared__ float Bs[32][33];

    const int tx = threadIdx.x & 15;
    const int ty = threadIdx.x >> 4;

    // cooperative tile load indexing: 256 threads -> 32 rows x 8 float4 groups
    const int lr = threadIdx.x >> 3;          // 0..31
    const int lc = (threadIdx.x & 7) * 4;     // 0,4,...,28

    float a00 = 0.f, a01 = 0.f, a10 = 0.f, a11 = 0.f;

    for (int k0 = 0; k0 < NN; k0 += 32) {
        float4 av = *(const float4*)&g_L[(size_t)(bi * 32 + lr) * NN + k0 + lc];
        float4 bv = *(const float4*)&g_L[(size_t)(bj * 32 + lr) * NN + k0 + lc];
        As[lr][lc] = av.x; As[lr][lc + 1] = av.y; As[lr][lc + 2] = av.z; As[lr][lc + 3] = av.w;
        Bs[lr][lc] = bv.x; Bs[lr][lc + 1] = bv.y; Bs[lr][lc + 2] = bv.z; Bs[lr][lc + 3] = bv.w;
        __syncthreads();

#pragma unroll
        for (int kk = 0; kk < 32; ++kk) {
            float x0 = As[2 * ty][kk];
            float x1 = As[2 * ty + 1][kk];
            float y0 = Bs[2 * tx][kk];
            float y1 = Bs[2 * tx + 1][kk];
            a00 += x0 * y0;
            a01 += x0 * y1;
            a10 += x1 * y0;
            a11 += x1 * y1;
        }
        __syncthreads();
    }

    const int R = bi * 32 + 2 * ty;
    const int C = bj * 32 + 2 * tx;
    D[(size_t)R * NN + C]           = a00;
    D[(size_t)R * NN + C + 1]       = a01;
    D[(size_t)(R + 1) * NN + C]     = a10;
    D[(size_t)(R + 1) * NN + C + 1] = a11;
    if (bi != bj) {   // mirror (D symmetric)
        D[(size_t)C * NN + R]           = a00;
        D[(size_t)(C + 1) * NN + R]     = a01;
        D[(size_t)C * NN + R + 1]       = a10;
        D[(size_t)(C + 1) * NN + R + 1] = a11;
    }
}

// ---------------------------------------------------------------------------
extern "C" void kernel_launch(void* const* d_in, const int* in_sizes, int n_in,
                              void* d_out, int out_size) {
    const float* input = (const float*)d_in[0];
    const float* W0    = (const float*)d_in[1];
    const float* b0    = (const float*)d_in[2];
    const float* W1    = (const float*)d_in[3];
    const float* b1    = (const float*)d_in[4];
    const float* W2    = (const float*)d_in[5];
    const float* b2    = (const float*)d_in[6];
    const float* Wo    = (const float*)d_in[7];
    const float* bo    = (const float*)d_in[8];
    float* out = (float*)d_out;

    // MLP: three tanh layers (device-global outputs selected via templates)
    mlp_layer<512, -1, 0><<<32, 256>>>(input, W0, b0);
    mlp_layer<1024, 0, 1><<<32, 256>>>(nullptr, W1, b1);
    mlp_layer<1024, 1, 2><<<32, 256>>>(nullptr, W2, b2);

    // Dominant GEMV over Wo (537 MB stream)
    gemv_out<<<(OUT4 + 255) / 256, 256>>>(Wo, bo);

    // Assemble L
    build_L<<<(NN * NN) / 256, 256>>>();

    // D = L L^T
    dim3 g(16, 16);
    gemm_llt<<<g, 256>>>(out);
}

// round 3
// speedup vs baseline: 1.5820x; 1.5820x over previous
#include <cuda_runtime.h>
#include <math.h>

// Problem constants
#define NN     512
#define HID    1024
#define OUTD   131328          // N + N*(N-1)/2
#define OUT4   (OUTD / 4)      // 32832 float4 columns
#define SPLITK 8
#define JCH    (HID / SPLITK)  // 128 rows of Wo per k-chunk

// Device scratch (no allocation allowed). Referenced ONLY in device code.
__device__ float g_h[3][HID];            // h0, h1, h2
__device__ float g_part[SPLITK][OUTD];   // split-K partial sums of big GEMV
__device__ float g_L[NN * NN];

// ---------------------------------------------------------------------------
// MLP layer: out[j] = tanh(b[j] + sum_i x[i] * W[i][j]),  W row-major [IN,1024]
// Block = 256 threads (8 warps). Warp w covers i in [w*IN/8, (w+1)*IN/8).
// Each lane owns output column j = blockIdx.x*32 + lane (coalesced W reads).
// SRC: -1 = external x pointer, else g_h[SRC]. DST: index into g_h.
// ---------------------------------------------------------------------------
template <int IN, int SRC, int DST>
__global__ void mlp_layer(const float* __restrict__ x_ext,
                          const float* __restrict__ W,
                          const float* __restrict__ b) {
    const float* x = (SRC < 0) ? x_ext : g_h[SRC];
    const int lane = threadIdx.x & 31;
    const int w    = threadIdx.x >> 5;
    const int j    = blockIdx.x * 32 + lane;
    const int CH   = IN / 8;
    const int i0   = w * CH;

    float acc = 0.f;
#pragma unroll 8
    for (int i = 0; i < CH; ++i) {
        acc += x[i0 + i] * __ldg(&W[(size_t)(i0 + i) * 1024 + j]);
    }

    __shared__ float sh[8][32];
    sh[w][lane] = acc;
    __syncthreads();
    if (w == 0) {
        float s = 0.f;
#pragma unroll
        for (int q = 0; q < 8; ++q) s += sh[q][lane];
        g_h[DST][j] = tanhf(s + __ldg(&b[j]));
    }
}

// ---------------------------------------------------------------------------
// Big GEMV, split-K: partial[chunk][k] = sum_{j in chunk} h2[j] * Wo[j][k]
// grid = (129, SPLITK), block = 256. One float4 column per thread per chunk.
// 1032 CTAs -> ~7 CTAs/SM -> enough in-flight LDG.128 to saturate HBM.
// ---------------------------------------------------------------------------
__global__ void gemv_out(const float* __restrict__ Wo) {
    const int chunk = blockIdx.y;

    __shared__ float hs[JCH];
    if (threadIdx.x < JCH) hs[threadIdx.x] = g_h[2][chunk * JCH + threadIdx.x];
    __syncthreads();

    const int k4 = blockIdx.x * blockDim.x + threadIdx.x;
    if (k4 >= OUT4) return;

    const float4* W4 = (const float4*)Wo + (size_t)chunk * JCH * OUT4;
    float ax = 0.f, ay = 0.f, az = 0.f, aw = 0.f;

#pragma unroll 8
    for (int j = 0; j < JCH; ++j) {
        float4 wv = __ldg(&W4[(size_t)j * OUT4 + k4]);
        float  hj = hs[j];
        ax += hj * wv.x;
        ay += hj * wv.y;
        az += hj * wv.z;
        aw += hj * wv.w;
    }

    float4 r; r.x = ax; r.y = ay; r.z = az; r.w = aw;
    ((float4*)g_part[chunk])[k4] = r;
}

// ---------------------------------------------------------------------------
// Assemble L, fusing the split-K reduction + bias:
//   o[k] = bo[k] + sum_q part[q][k]
//   diag = exp(o[:N]); strict lower from o[N:] in tril-index order; upper = 0.
// Warp lanes share r, consecutive c -> partial reads are coalesced.
// ---------------------------------------------------------------------------
__global__ void build_L(const float* __restrict__ bo) {
    const int idx = blockIdx.x * 256 + threadIdx.x;   // < 512*512
    const int r = idx >> 9;
    const int c = idx & 511;
    if (c > r) { g_L[idx] = 0.f; return; }

    const int k = (c < r) ? (NN + (r * (r - 1)) / 2 + c) : r;
    float s = __ldg(&bo[k]);
#pragma unroll
    for (int q = 0; q < SPLITK; ++q) s += g_part[q][k];

    g_L[idx] = (c < r) ? s : expf(s);
}

// ---------------------------------------------------------------------------
// D = L * L^T (symmetric). 32x32 output tiles; upper-triangle blocks exit;
// lower/diag blocks computed, off-diag mirrored on store. 2x2 microtile.
// Tiles stored k-major (transposed) with pad 34 so the inner loop does
// float2 LDS.64 instead of 2 scalar LDS.
// ---------------------------------------------------------------------------
__global__ void gemm_llt(float* __restrict__ D) {
    const int bi = blockIdx.y;   // row tile
    const int bj = blockIdx.x;   // col tile
    if (bj > bi) return;

    __shared__ float As[32][34];   // As[kk][row]
    __shared__ float Bs[32][34];   // Bs[kk][col]

    const int tx = threadIdx.x & 15;
    const int ty = threadIdx.x >> 4;

    // cooperative tile load indexing: 256 threads -> 32 rows x 8 float4 groups
    const int lr = threadIdx.x >> 3;          // 0..31
    const int lc = (threadIdx.x & 7) * 4;     // 0,4,...,28

    float a00 = 0.f, a01 = 0.f, a10 = 0.f, a11 = 0.f;

    for (int k0 = 0; k0 < NN; k0 += 32) {
        float4 av = *(const float4*)&g_L[(size_t)(bi * 32 + lr) * NN + k0 + lc];
        float4 bv = *(const float4*)&g_L[(size_t)(bj * 32 + lr) * NN + k0 + lc];
        As[lc][lr] = av.x; As[lc + 1][lr] = av.y; As[lc + 2][lr] = av.z; As[lc + 3][lr] = av.w;
        Bs[lc][lr] = bv.x; Bs[lc + 1][lr] = bv.y; Bs[lc + 2][lr] = bv.z; Bs[lc + 3][lr] = bv.w;
        __syncthreads();

#pragma unroll
        for (int kk = 0; kk < 32; ++kk) {
            float2 xv = *(const float2*)&As[kk][2 * ty];
            float2 yv = *(const float2*)&Bs[kk][2 * tx];
            a00 += xv.x * yv.x;
            a01 += xv.x * yv.y;
            a10 += xv.y * yv.x;
            a11 += xv.y * yv.y;
        }
        __syncthreads();
    }

    const int R = bi * 32 + 2 * ty;
    const int C = bj * 32 + 2 * tx;
    D[(size_t)R * NN + C]           = a00;
    D[(size_t)R * NN + C + 1]       = a01;
    D[(size_t)(R + 1) * NN + C]     = a10;
    D[(size_t)(R + 1) * NN + C + 1] = a11;
    if (bi != bj) {   // mirror (D symmetric)
        D[(size_t)C * NN + R]           = a00;
        D[(size_t)(C + 1) * NN + R]     = a01;
        D[(size_t)C * NN + R + 1]       = a10;
        D[(size_t)(C + 1) * NN + R + 1] = a11;
    }
}

// ---------------------------------------------------------------------------
extern "C" void kernel_launch(void* const* d_in, const int* in_sizes, int n_in,
                              void* d_out, int out_size) {
    const float* input = (const float*)d_in[0];
    const float* W0    = (const float*)d_in[1];
    const float* b0    = (const float*)d_in[2];
    const float* W1    = (const float*)d_in[3];
    const float* b1    = (const float*)d_in[4];
    const float* W2    = (const float*)d_in[5];
    const float* b2    = (const float*)d_in[6];
    const float* Wo    = (const float*)d_in[7];
    const float* bo    = (const float*)d_in[8];
    float* out = (float*)d_out;

    // MLP: three tanh layers (device-global outputs selected via templates)
    mlp_layer<512, -1, 0><<<32, 256>>>(input, W0, b0);
    mlp_layer<1024, 0, 1><<<32, 256>>>(nullptr, W1, b1);
    mlp_layer<1024, 1, 2><<<32, 256>>>(nullptr, W2, b2);

    // Dominant GEMV over Wo (537 MB stream), split-K for occupancy
    dim3 gv((OUT4 + 255) / 256, SPLITK);
    gemv_out<<<gv, 256>>>(Wo);

    // Assemble L (fuses split-K reduction + bias)
    build_L<<<(NN * NN) / 256, 256>>>(bo);

    // D = L L^T
    dim3 g(16, 16);
    gemm_llt<<<g, 256>>>(out);
}

// round 4
// speedup vs baseline: 1.8191x; 1.1499x over previous
#include <cuda_runtime.h>
#include <math.h>

// Problem constants
#define NN     512
#define HID    1024
#define OUTD   131328          // N + N*(N-1)/2
#define OUT4   (OUTD / 4)      // 32832 float4 columns
#define SPLITK 16
#define JCH    (HID / SPLITK)  // 64 rows of Wo per k-chunk
#define SI     4               // split-i factor for MLP layers

// Device scratch (no allocation allowed). Referenced ONLY in device code.
__device__ float g_hp[3][SI][HID];       // per-layer split-i partials (pre-bias, pre-tanh)
__device__ float g_part[SPLITK][OUTD];   // split-K partial sums of big GEMV
__device__ float g_L[NN * NN];

// ---------------------------------------------------------------------------
// MLP layer (split-i): partial[DST][chunk][j] = sum_{i in chunk} x[i]*W[i][j]
// where x = tanh(b_prev + sum_q partial[SRC][q][:]) (fused input reduction),
// or the raw external input when SRC < 0.
// grid = (32, SI), block = 256 (8 warps). Each block covers one i-chunk of
// IN/SI rows; warp w covers an IN/(SI*8) sub-slice; lane owns column j.
// ---------------------------------------------------------------------------
template <int IN, int SRC, int DST>
__global__ void mlp_layer(const float* __restrict__ x_ext,
                          const float* __restrict__ W,
                          const float* __restrict__ bprev) {
    const int CHUNK = IN / SI;        // i-rows this block handles
    const int chunk = blockIdx.y;
    const int base  = chunk * CHUNK;

    __shared__ float xs[CHUNK];
    for (int t = threadIdx.x; t < CHUNK; t += 256) {
        if (SRC < 0) {
            xs[t] = x_ext[base + t];
        } else {
            float s = __ldg(&bprev[base + t]);
#pragma unroll
            for (int q = 0; q < SI; ++q) s += g_hp[SRC][q][base + t];
            xs[t] = tanhf(s);
        }
    }
    __syncthreads();

    const int lane = threadIdx.x & 31;
    const int w    = threadIdx.x >> 5;
    const int j    = blockIdx.x * 32 + lane;
    const int CH   = CHUNK / 8;
    const int i0   = w * CH;

    float acc = 0.f;
#pragma unroll 8
    for (int i = 0; i < CH; ++i) {
        acc += xs[i0 + i] * __ldg(&W[(size_t)(base + i0 + i) * 1024 + j]);
    }

    __shared__ float sh[8][32];
    sh[w][lane] = acc;
    __syncthreads();
    if (w == 0) {
        float s = 0.f;
#pragma unroll
        for (int q = 0; q < 8; ++q) s += sh[q][lane];
        g_hp[DST][chunk][j] = s;   // bias+tanh fused into the consumer
    }
}

// ---------------------------------------------------------------------------
// Big GEMV, split-K: part[chunk][k] = sum_{j in chunk} h2[j] * Wo[j][k]
// h2 = tanh(b2 + sum_q g_hp[2][q][:]) fused at the shared-staging load.
// grid = (129, SPLITK), block = 256. One float4 column per thread per chunk.
// ---------------------------------------------------------------------------
__global__ void gemv_out(const float* __restrict__ Wo,
                         const float* __restrict__ b2) {
    const int chunk = blockIdx.y;

    __shared__ float hs[JCH];
    if (threadIdx.x < JCH) {
        const int t = chunk * JCH + threadIdx.x;
        float s = __ldg(&b2[t]);
#pragma unroll
        for (int q = 0; q < SI; ++q) s += g_hp[2][q][t];
        hs[threadIdx.x] = tanhf(s);
    }
    __syncthreads();

    const int k4 = blockIdx.x * blockDim.x + threadIdx.x;
    if (k4 >= OUT4) return;

    const float4* W4 = (const float4*)Wo + (size_t)chunk * JCH * OUT4;
    float ax = 0.f, ay = 0.f, az = 0.f, aw = 0.f;

#pragma unroll 8
    for (int j = 0; j < JCH; ++j) {
        float4 wv = __ldg(&W4[(size_t)j * OUT4 + k4]);
        float  hj = hs[j];
        ax += hj * wv.x;
        ay += hj * wv.y;
        az += hj * wv.z;
        aw += hj * wv.w;
    }

    float4 r; r.x = ax; r.y = ay; r.z = az; r.w = aw;
    ((float4*)g_part[chunk])[k4] = r;
}

// ---------------------------------------------------------------------------
// Assemble L, fusing the split-K reduction + bias:
//   o[k] = bo[k] + sum_q part[q][k]
//   diag = exp(o[:N]); strict lower from o[N:] in tril order; upper = 0.
// ---------------------------------------------------------------------------
__global__ void build_L(const float* __restrict__ bo) {
    const int idx = blockIdx.x * 256 + threadIdx.x;   // < 512*512
    const int r = idx >> 9;
    const int c = idx & 511;
    if (c > r) { g_L[idx] = 0.f; return; }

    const int k = (c < r) ? (NN + (r * (r - 1)) / 2 + c) : r;
    float s = __ldg(&bo[k]);
#pragma unroll
    for (int q = 0; q < SPLITK; ++q) s += g_part[q][k];

    g_L[idx] = (c < r) ? s : expf(s);
}

// ---------------------------------------------------------------------------
// D = L * L^T (symmetric). 32x32 output tiles; upper-triangle blocks exit;
// lower/diag computed, off-diag mirrored on store. 2x2 microtile, k-major
// smem tiles (pad 34) so the inner loop uses float2 LDS.64.
// ---------------------------------------------------------------------------
__global__ void gemm_llt(float* __restrict__ D) {
    const int bi = blockIdx.y;
    const int bj = blockIdx.x;
    if (bj > bi) return;

    __shared__ float As[32][34];   // As[kk][row]
    __shared__ float Bs[32][34];   // Bs[kk][col]

    const int tx = threadIdx.x & 15;
    const int ty = threadIdx.x >> 4;

    const int lr = threadIdx.x >> 3;          // 0..31
    const int lc = (threadIdx.x & 7) * 4;     // 0,4,...,28

    float a00 = 0.f, a01 = 0.f, a10 = 0.f, a11 = 0.f;

    for (int k0 = 0; k0 < NN; k0 += 32) {
        float4 av = *(const float4*)&g_L[(size_t)(bi * 32 + lr) * NN + k0 + lc];
        float4 bv = *(const float4*)&g_L[(size_t)(bj * 32 + lr) * NN + k0 + lc];
        As[lc][lr] = av.x; As[lc + 1][lr] = av.y; As[lc + 2][lr] = av.z; As[lc + 3][lr] = av.w;
        Bs[lc][lr] = bv.x; Bs[lc + 1][lr] = bv.y; Bs[lc + 2][lr] = bv.z; Bs[lc + 3][lr] = bv.w;
        __syncthreads();

#pragma unroll
        for (int kk = 0; kk < 32; ++kk) {
            float2 xv = *(const float2*)&As[kk][2 * ty];
            float2 yv = *(const float2*)&Bs[kk][2 * tx];
            a00 += xv.x * yv.x;
            a01 += xv.x * yv.y;
            a10 += xv.y * yv.x;
            a11 += xv.y * yv.y;
        }
        __syncthreads();
    }

    const int R = bi * 32 + 2 * ty;
    const int C = bj * 32 + 2 * tx;
    D[(size_t)R * NN + C]           = a00;
    D[(size_t)R * NN + C + 1]       = a01;
    D[(size_t)(R + 1) * NN + C]     = a10;
    D[(size_t)(R + 1) * NN + C + 1] = a11;
    if (bi != bj) {
        D[(size_t)C * NN + R]           = a00;
        D[(size_t)(C + 1) * NN + R]     = a01;
        D[(size_t)C * NN + R + 1]       = a10;
        D[(size_t)(C + 1) * NN + R + 1] = a11;
    }
}

// ---------------------------------------------------------------------------
extern "C" void kernel_launch(void* const* d_in, const int* in_sizes, int n_in,
                              void* d_out, int out_size) {
    const float* input = (const float*)d_in[0];
    const float* W0    = (const float*)d_in[1];
    // b0/b1/b2 are consumed as "previous-layer bias" by the next kernel.
    const float* b0    = (const float*)d_in[2];
    const float* W1    = (const float*)d_in[3];
    const float* b1    = (const float*)d_in[4];
    const float* W2    = (const float*)d_in[5];
    const float* b2    = (const float*)d_in[6];
    const float* Wo    = (const float*)d_in[7];
    const float* bo    = (const float*)d_in[8];
    float* out = (float*)d_out;

    dim3 gm(32, SI);
    mlp_layer<512,  -1, 0><<<gm, 256>>>(input,   W0, nullptr);
    mlp_layer<1024,  0, 1><<<gm, 256>>>(nullptr, W1, b0);
    mlp_layer<1024,  1, 2><<<gm, 256>>>(nullptr, W2, b1);

    // Dominant GEMV over Wo (537 MB stream), split-K for occupancy.
    // Fuses tanh(b2 + partials) at its input staging.
    dim3 gv((OUT4 + 255) / 256, SPLITK);
    gemv_out<<<gv, 256>>>(Wo, b2);

    // Assemble L (fuses split-K reduction + bias)
    build_L<<<(NN * NN) / 256, 256>>>(bo);

    // D = L L^T
    dim3 g(16, 16);
    gemm_llt<<<g, 256>>>(out);
}

// round 5
// speedup vs baseline: 1.9577x; 1.0762x over previous
#include <cuda_runtime.h>
#include <math.h>

// Problem constants
#define NN     512
#define HID    1024
#define OUTD   131328          // N + N*(N-1)/2
#define OUT4   (OUTD / 4)      // 32832 float4 columns
#define SPLITK 8
#define JCH    (HID / SPLITK)  // 128 rows of Wo per k-chunk
#define SI     8               // split-i factor for MLP layers

// Device scratch (no allocation allowed). Referenced ONLY in device code.
__device__ float g_hp[3][SI][HID];       // per-layer split-i partials (pre-bias, pre-tanh)
__device__ float g_part[SPLITK][OUTD];   // split-K partial sums of big GEMV
__device__ float g_L[NN * NN];

// ---------------------------------------------------------------------------
// MLP layer (split-i): partial[DST][chunk][j] = sum_{i in chunk} x[i]*W[i][j]
// x = tanh(b_prev + sum_q partial[SRC][q][:]) fused at input staging,
// or raw external input when SRC < 0.
// grid = (32, SI), block = 256 (8 warps).
// ---------------------------------------------------------------------------
template <int IN, int SRC, int DST>
__global__ void mlp_layer(const float* __restrict__ x_ext,
                          const float* __restrict__ W,
                          const float* __restrict__ bprev) {
    const int CHUNK = IN / SI;
    const int chunk = blockIdx.y;
    const int base  = chunk * CHUNK;

    __shared__ float xs[CHUNK];
    for (int t = threadIdx.x; t < CHUNK; t += 256) {
        if (SRC < 0) {
            xs[t] = x_ext[base + t];
        } else {
            float s = __ldg(&bprev[base + t]);
#pragma unroll
            for (int q = 0; q < SI; ++q) s += g_hp[SRC][q][base + t];
            xs[t] = tanhf(s);
        }
    }
    __syncthreads();

    const int lane = threadIdx.x & 31;
    const int w    = threadIdx.x >> 5;
    const int j    = blockIdx.x * 32 + lane;
    const int CH   = CHUNK / 8;
    const int i0   = w * CH;

    float acc = 0.f;
#pragma unroll
    for (int i = 0; i < CH; ++i) {
        acc += xs[i0 + i] * __ldg(&W[(size_t)(base + i0 + i) * 1024 + j]);
    }

    __shared__ float sh[8][32];
    sh[w][lane] = acc;
    __syncthreads();
    if (w == 0) {
        float s = 0.f;
#pragma unroll
        for (int q = 0; q < 8; ++q) s += sh[q][lane];
        g_hp[DST][chunk][j] = s;   // bias+tanh fused into the consumer
    }
}

// ---------------------------------------------------------------------------
// Big GEMV, split-K: part[chunk][k] = sum_{j in chunk} h2[j] * Wo[j][k]
// h2 = tanh(b2 + sum_q g_hp[2][q][:]) fused at staging.
// grid = (129, SPLITK), block = 256.
// ---------------------------------------------------------------------------
__global__ void gemv_out(const float* __restrict__ Wo,
                         const float* __restrict__ b2) {
    const int chunk = blockIdx.y;

    __shared__ float hs[JCH];
    if (threadIdx.x < JCH) {
        const int t = chunk * JCH + threadIdx.x;
        float s = __ldg(&b2[t]);
#pragma unroll
        for (int q = 0; q < SI; ++q) s += g_hp[2][q][t];
        hs[threadIdx.x] = tanhf(s);
    }
    __syncthreads();

    const int k4 = blockIdx.x * blockDim.x + threadIdx.x;
    if (k4 >= OUT4) return;

    const float4* W4 = (const float4*)Wo + (size_t)chunk * JCH * OUT4;
    float ax = 0.f, ay = 0.f, az = 0.f, aw = 0.f;

#pragma unroll 8
    for (int j = 0; j < JCH; ++j) {
        float4 wv = __ldg(&W4[(size_t)j * OUT4 + k4]);
        float  hj = hs[j];
        ax += hj * wv.x;
        ay += hj * wv.y;
        az += hj * wv.z;
        aw += hj * wv.w;
    }

    float4 r; r.x = ax; r.y = ay; r.z = az; r.w = aw;
    ((float4*)g_part[chunk])[k4] = r;
}

// ---------------------------------------------------------------------------
// Assemble L, fusing the split-K reduction + bias.
// ---------------------------------------------------------------------------
__global__ void build_L(const float* __restrict__ bo) {
    const int idx = blockIdx.x * 256 + threadIdx.x;   // < 512*512
    const int r = idx >> 9;
    const int c = idx & 511;
    if (c > r) { g_L[idx] = 0.f; return; }

    const int k = (c < r) ? (NN + (r * (r - 1)) / 2 + c) : r;
    float s = __ldg(&bo[k]);
#pragma unroll
    for (int q = 0; q < SPLITK; ++q) s += g_part[q][k];

    g_L[idx] = (c < r) ? s : expf(s);
}

// ---------------------------------------------------------------------------
// D = L * L^T (symmetric). 32x32 output tiles, upper blocks exit, mirror on
// store. L[c][k] = 0 for k > c, so tile (bi,bj) only needs k < (bj+1)*32 —
// 3x fewer MACs than the full-k version.
// 128 threads: two 64-thread k-groups (even/odd 32-slices of each 64-slab),
// each thread a 4x4 microtile via float4 LDS; groups combined via smem.
// ---------------------------------------------------------------------------
__global__ void gemm_llt(float* __restrict__ D) {
    const int bi = blockIdx.y;
    const int bj = blockIdx.x;
    if (bj > bi) return;

    __shared__ float As[64][36];   // As[kk][row], 36-pad keeps float4 alignment
    __shared__ float Bs[64][36];   // Bs[kk][col]
    __shared__ float red[64][16];  // group-1 accumulators for final combine

    const int tid  = threadIdx.x;        // 0..127
    const int grp  = tid >> 6;            // 0 or 1
    const int id64 = tid & 63;
    const int tx   = id64 & 7;            // col group (4 cols)
    const int ty   = id64 >> 3;           // row group (4 rows)

    // load mapping: thread -> row = tid>>2 (0..31), 16 consecutive cols
    const int lr = tid >> 2;
    const int lc = (tid & 3) * 16;

    float acc[4][4];
#pragma unroll
    for (int i = 0; i < 4; ++i)
#pragma unroll
        for (int j = 0; j < 4; ++j) acc[i][j] = 0.f;

    const int nslab = (bj >> 1) + 1;      // 64-wide k slabs; covers k <= bj*32+31

    for (int s = 0; s < nslab; ++s) {
        const int k0 = s * 64;
        // load 32x64 slabs of A-rows and B-rows (cols k0..k0+63)
#pragma unroll
        for (int q = 0; q < 4; ++q) {
            float4 av = *(const float4*)&g_L[(size_t)(bi * 32 + lr) * NN + k0 + lc + 4 * q];
            float4 bv = *(const float4*)&g_L[(size_t)(bj * 32 + lr) * NN + k0 + lc + 4 * q];
            const int c = lc + 4 * q;
            As[c][lr] = av.x; As[c + 1][lr] = av.y; As[c + 2][lr] = av.z; As[c + 3][lr] = av.w;
            Bs[c][lr] = bv.x; Bs[c + 1][lr] = bv.y; Bs[c + 2][lr] = bv.z; Bs[c + 3][lr] = bv.w;
        }
        __syncthreads();

        const int kb = grp * 32;
#pragma unroll
        for (int kk = 0; kk < 32; ++kk) {
            float4 a = *(const float4*)&As[kb + kk][ty * 4];
            float4 b = *(const float4*)&Bs[kb + kk][tx * 4];
            acc[0][0] += a.x * b.x; acc[0][1] += a.x * b.y; acc[0][2] += a.x * b.z; acc[0][3] += a.x * b.w;
            acc[1][0] += a.y * b.x; acc[1][1] += a.y * b.y; acc[1][2] += a.y * b.z; acc[1][3] += a.y * b.w;
            acc[2][0] += a.z * b.x; acc[2][1] += a.z * b.y; acc[2][2] += a.z * b.z; acc[2][3] += a.z * b.w;
            acc[3][0] += a.w * b.x; acc[3][1] += a.w * b.y; acc[3][2] += a.w * b.z; acc[3][3] += a.w * b.w;
        }
        __syncthreads();
    }

    // combine group 1 into group 0
    if (grp == 1) {
#pragma unroll
        for (int i = 0; i < 4; ++i)
#pragma unroll
            for (int j = 0; j < 4; ++j) red[id64][i * 4 + j] = acc[i][j];
    }
    __syncthreads();
    if (grp == 0) {
#pragma unroll
        for (int i = 0; i < 4; ++i)
#pragma unroll
            for (int j = 0; j < 4; ++j) acc[i][j] += red[id64][i * 4 + j];

        const int R = bi * 32 + ty * 4;
        const int C = bj * 32 + tx * 4;
#pragma unroll
        for (int i = 0; i < 4; ++i) {
            float4 v; v.x = acc[i][0]; v.y = acc[i][1]; v.z = acc[i][2]; v.w = acc[i][3];
            *(float4*)&D[(size_t)(R + i) * NN + C] = v;
        }
        if (bi != bj) {   // mirror (transposed microtile, float4 rows)
#pragma unroll
            for (int j = 0; j < 4; ++j) {
                float4 v; v.x = acc[0][j]; v.y = acc[1][j]; v.z = acc[2][j]; v.w = acc[3][j];
                *(float4*)&D[(size_t)(C + j) * NN + R] = v;
            }
        }
    }
}

// ---------------------------------------------------------------------------
extern "C" void kernel_launch(void* const* d_in, const int* in_sizes, int n_in,
                              void* d_out, int out_size) {
    const float* input = (const float*)d_in[0];
    const float* W0    = (const float*)d_in[1];
    const float* b0    = (const float*)d_in[2];
    const float* W1    = (const float*)d_in[3];
    const float* b1    = (const float*)d_in[4];
    const float* W2    = (const float*)d_in[5];
    const float* b2    = (const float*)d_in[6];
    const float* Wo    = (const float*)d_in[7];
    const float* bo    = (const float*)d_in[8];
    float* out = (float*)d_out;

    dim3 gm(32, SI);
    mlp_layer<512,  -1, 0><<<gm, 256>>>(input,   W0, nullptr);
    mlp_layer<1024,  0, 1><<<gm, 256>>>(nullptr, W1, b0);
    mlp_layer<1024,  1, 2><<<gm, 256>>>(nullptr, W2, b1);

    // Dominant GEMV over Wo (537 MB stream); fuses tanh(b2 + partials).
    dim3 gv((OUT4 + 255) / 256, SPLITK);
    gemv_out<<<gv, 256>>>(Wo, b2);

    // Assemble L (fuses split-K reduction + bias)
    build_L<<<(NN * NN) / 256, 256>>>(bo);

    // D = L L^T (triangular-k)
    dim3 g(16, 16);
    gemm_llt<<<g, 128>>>(out);
}